// round 6
// baseline (speedup 1.0000x reference)
#include <cuda_runtime.h>
#include <cuda_bf16.h>
#include <cstdint>

#define N_NODES  30000
#define N_EDGES  300000
#define N_GRAPHS 128
#define DIM      128

// ---------------------------------------------------------------------------
// Scratch: __device__ globals, referenced ONLY from device code.
// kernel_launch makes no CUDA runtime API calls at all (launches only).
// ---------------------------------------------------------------------------
__device__ float g_bufA[(size_t)N_EDGES * 256];   // hidden ping (307 MB)
__device__ float g_bufB[(size_t)N_EDGES * 256];   // hidden pong (307 MB)
__device__ float g_agg[(size_t)N_NODES * DIM];    // scatter-sum of edges_out by col
__device__ float g_cnt[N_NODES];                  // edge count per node
__device__ float g_gsn[N_GRAPHS * DIM];           // per-graph node sums
__device__ float g_gse[N_GRAPHS * DIM];           // per-graph edge sums
__device__ float g_gcn[N_GRAPHS];                 // per-graph node counts
__device__ float g_gce[N_GRAPHS];                 // per-graph edge counts
__device__ float g_gin[N_GRAPHS * 384];           // global MLP input
__device__ float g_gh0[N_GRAPHS * 256];
__device__ float g_gh1[N_GRAPHS * 256];

// device-side scratch selector (avoids cudaGetSymbolAddress on host)
__device__ __forceinline__ float* buf_ptr(int sel, float* def) {
    if (sel == 0) return g_bufA;
    if (sel == 1) return g_bufB;
    return def;
}
__device__ __forceinline__ const float* cbuf_ptr(int sel, const float* def) {
    if (sel == 0) return g_bufA;
    if (sel == 1) return g_bufB;
    if (sel == 2) return g_gin;
    if (sel == 3) return g_gh0;
    if (sel == 4) return g_gh1;
    return def;
}

// ---------------------------------------------------------------------------
// packed fp32x2 FMA (Blackwell; 2x fp32 throughput vs scalar FFMA)
// ---------------------------------------------------------------------------
__device__ __forceinline__ void ffma2(unsigned long long& d,
                                      unsigned long long a,
                                      unsigned long long b) {
    asm("fma.rn.f32x2 %0, %1, %2, %0;" : "+l"(d) : "l"(a), "l"(b));
}

// ---------------------------------------------------------------------------
// Zero all accumulators in one kernel (flattened ranges, globals direct)
// ---------------------------------------------------------------------------
#define NZ_AGG (N_NODES * DIM)                       // 3,840,000
#define NZ_1   (NZ_AGG + N_NODES)                    // + cnt
#define NZ_2   (NZ_1 + N_GRAPHS * DIM)               // + gsn
#define NZ_3   (NZ_2 + N_GRAPHS * DIM)               // + gse
#define NZ_4   (NZ_3 + N_GRAPHS)                     // + gcn
#define NZ_TOT (NZ_4 + N_GRAPHS)                     // + gce

__global__ void zero_all_kernel() {
    int i = blockIdx.x * blockDim.x + threadIdx.x;
    if (i < NZ_AGG)      g_agg[i] = 0.0f;
    else if (i < NZ_1)   g_cnt[i - NZ_AGG] = 0.0f;
    else if (i < NZ_2)   g_gsn[i - NZ_1] = 0.0f;
    else if (i < NZ_3)   g_gse[i - NZ_2] = 0.0f;
    else if (i < NZ_4)   g_gcn[i - NZ_3] = 0.0f;
    else if (i < NZ_TOT) g_gce[i - NZ_4] = 0.0f;
}

// ---------------------------------------------------------------------------
// Fused-gather tiled GEMM:  out[M,N] = act(X[M,K] @ W[K,N] + b)
// MODE 0: dense X
// MODE 1: edge gather (K=512): [nodes[row] | nodes[col] | eattr | u[batch[row]]]
// MODE 2: node gather (K=384): [nodes | agg/max(cnt,1) | u[batch]]
// BM=BN=128, BK=16, 256 threads, 8x8 outputs/thread as 4x8 f32x2 pairs.
// NOTE: edge_index / batch are int32 (JAX default x64-disabled downcasts int64).
// ---------------------------------------------------------------------------
template <int MODE>
__device__ __forceinline__ float load_x(
    int m, int k,
    const float* __restrict__ X, int ldx,
    const float* __restrict__ nodes,
    const int* __restrict__ erow, const int* __restrict__ ecol,
    const float* __restrict__ eattr,
    const float* __restrict__ u, const int* __restrict__ batch) {
    if (MODE == 0) {
        return X[(size_t)m * ldx + k];
    } else if (MODE == 1) {
        if (k < 128) {
            int r = erow[m];
            return nodes[(size_t)r * 128 + k];
        } else if (k < 256) {
            int c = ecol[m];
            return nodes[(size_t)c * 128 + (k - 128)];
        } else if (k < 384) {
            return eattr[(size_t)m * 128 + (k - 256)];
        } else {
            int r = erow[m];
            int g = batch[r];
            return u[g * 128 + (k - 384)];
        }
    } else {
        if (k < 128) {
            return nodes[(size_t)m * 128 + k];
        } else if (k < 256) {
            float r = __frcp_rn(fmaxf(g_cnt[m], 1.0f));
            return g_agg[(size_t)m * 128 + (k - 128)] * r;
        } else {
            int g = batch[m];
            return u[g * 128 + (k - 256)];
        }
    }
}

template <int MODE, bool RELU>
__global__ void __launch_bounds__(256)
gemm_kernel(int M, int K, int N,
            const float* __restrict__ W, const float* __restrict__ bias,
            int xsel, const float* Xdef, int ldx,
            int osel, float* Odef,
            const float* __restrict__ nodes,
            const int* __restrict__ erow, const int* __restrict__ ecol,
            const float* __restrict__ eattr,
            const float* __restrict__ u, const int* __restrict__ batch) {
    constexpr int BM = 128, BN = 128, BK = 16;
    constexpr int XS_LD = 132;   // padded; keeps 16B alignment (132*4=528)
    constexpr int WS_LD = 256;   // broadcast-duplicated W row: [w0,w0,w1,w1,...]

    __shared__ __align__(16) float Xs[BK * XS_LD];
    __shared__ __align__(16) float Wsb[BK * WS_LD];

    const float* X = cbuf_ptr(xsel, Xdef);
    float* out = buf_ptr(osel, Odef);

    const int tid = threadIdx.x;
    const int tx = tid & 15;     // n-group: 8 cols
    const int ty = tid >> 4;     // m-group: 8 rows
    const int n0 = tx * 8;
    const int m0 = ty * 8;
    const int blockM = blockIdx.y * BM;
    const int blockN = blockIdx.x * BN;

    unsigned long long acc[4][8];
#pragma unroll
    for (int i = 0; i < 4; ++i)
#pragma unroll
        for (int j = 0; j < 8; ++j) acc[i][j] = 0ull;

    for (int k0 = 0; k0 < K; k0 += BK) {
        // X tile: gathered, transposed into SMEM [k][m]
#pragma unroll
        for (int it = 0; it < (BM * BK) / 256; ++it) {
            int i = tid + it * 256;
            int m = i >> 4;
            int k = i & 15;
            int gm = blockM + m;
            float v = 0.0f;
            if (gm < M)
                v = load_x<MODE>(gm, k0 + k, X, ldx, nodes, erow, ecol,
                                 eattr, u, batch);
            Xs[k * XS_LD + m] = v;
        }
        // W tile: each value duplicated into a 64-bit lane pair
#pragma unroll
        for (int it = 0; it < (BK * BN) / 256; ++it) {
            int i = tid + it * 256;
            int kk = i >> 7;
            int n = i & 127;
            float w = W[(size_t)(k0 + kk) * N + blockN + n];
            unsigned int ub = __float_as_uint(w);
            unsigned long long pr = ((unsigned long long)ub << 32) | (unsigned long long)ub;
            *(unsigned long long*)&Wsb[kk * WS_LD + 2 * n] = pr;
        }
        __syncthreads();

#pragma unroll
        for (int kk = 0; kk < BK; ++kk) {
            const float* xr = &Xs[kk * XS_LD + m0];
            ulonglong2 xa = *(const ulonglong2*)xr;          // rows m0..m0+3
            ulonglong2 xb = *(const ulonglong2*)(xr + 4);    // rows m0+4..m0+7
            unsigned long long xp[4] = {xa.x, xa.y, xb.x, xb.y};
            const ulonglong2* wr = (const ulonglong2*)&Wsb[kk * WS_LD + 2 * n0];
            ulonglong2 wA = wr[0], wB = wr[1], wC = wr[2], wD = wr[3];
            unsigned long long wp[8] = {wA.x, wA.y, wB.x, wB.y, wC.x, wC.y, wD.x, wD.y};
#pragma unroll
            for (int i = 0; i < 4; ++i)
#pragma unroll
                for (int j = 0; j < 8; ++j) ffma2(acc[i][j], xp[i], wp[j]);
        }
        __syncthreads();
    }

    // Epilogue: bias + activation + store (2 x float4 per row)
    float bv[8];
#pragma unroll
    for (int j = 0; j < 8; ++j) bv[j] = bias[blockN + n0 + j];

#pragma unroll
    for (int i = 0; i < 4; ++i) {
#pragma unroll
        for (int p = 0; p < 2; ++p) {
            int gm = blockM + m0 + 2 * i + p;
            if (gm >= M) continue;
            float vals[8];
#pragma unroll
            for (int j = 0; j < 8; ++j) {
                unsigned long long v = acc[i][j];
                unsigned int bits = p ? (unsigned int)(v >> 32) : (unsigned int)v;
                float f = __uint_as_float(bits) + bv[j];
                if (RELU) f = fmaxf(f, 0.0f);
                vals[j] = f;
            }
            float4* o = (float4*)&out[(size_t)gm * N + blockN + n0];
            o[0] = make_float4(vals[0], vals[1], vals[2], vals[3]);
            o[1] = make_float4(vals[4], vals[5], vals[6], vals[7]);
        }
    }
}

// ---------------------------------------------------------------------------
// Scatter kernels (atomics into __device__ globals)
// ---------------------------------------------------------------------------
__global__ void scatter_edges_kernel(const float* __restrict__ eo,
                                     const int* __restrict__ erow,
                                     const int* __restrict__ ecol,
                                     const int* __restrict__ batch) {
    long long idx = (long long)blockIdx.x * blockDim.x + threadIdx.x;
    if (idx >= (long long)N_EDGES * DIM) return;
    int e = (int)(idx >> 7);
    int d = (int)(idx & 127);
    float v = eo[idx];
    int c = ecol[e];
    atomicAdd(&g_agg[(size_t)c * 128 + d], v);
    int g = batch[erow[e]];
    atomicAdd(&g_gse[g * 128 + d], v);
    if (d == 0) {
        atomicAdd(&g_cnt[c], 1.0f);
        atomicAdd(&g_gce[g], 1.0f);
    }
}

__global__ void scatter_nodes_kernel(const float* __restrict__ no,
                                     const int* __restrict__ batch) {
    long long idx = (long long)blockIdx.x * blockDim.x + threadIdx.x;
    if (idx >= (long long)N_NODES * DIM) return;
    int n = (int)(idx >> 7);
    int d = (int)(idx & 127);
    float v = no[idx];
    int g = batch[n];
    atomicAdd(&g_gsn[g * 128 + d], v);
    if (d == 0) atomicAdd(&g_gcn[g], 1.0f);
}

__global__ void build_gin_kernel(const float* __restrict__ u) {
    int idx = blockIdx.x * blockDim.x + threadIdx.x;
    if (idx >= N_GRAPHS * 384) return;
    int g = idx / 384;
    int k = idx - g * 384;
    float v;
    if (k < 128) v = u[g * 128 + k];
    else if (k < 256) v = g_gsn[g * 128 + (k - 128)] / fmaxf(g_gcn[g], 1.0f);
    else v = g_gse[g * 128 + (k - 256)] / fmaxf(g_gce[g], 1.0f);
    g_gin[idx] = v;
}

// ---------------------------------------------------------------------------
// Tiny row-parallel MLP layer for the global model (M = 128 rows)
// one block per row, one thread per output column
// ---------------------------------------------------------------------------
template <bool RELU>
__global__ void small_mlp_kernel(int xsel, int K, int N,
                                 const float* __restrict__ W, const float* __restrict__ b,
                                 int osel, float* Odef) {
    __shared__ float xs[384];
    const float* X = cbuf_ptr(xsel, nullptr);
    float* out;
    if (osel == 3) out = g_gh0;
    else if (osel == 4) out = g_gh1;
    else out = Odef;
    int g = blockIdx.x;
    for (int k = threadIdx.x; k < K; k += blockDim.x) xs[k] = X[g * K + k];
    __syncthreads();
    int n = threadIdx.x;
    float acc = b[n];
#pragma unroll 4
    for (int k = 0; k < K; ++k) acc += xs[k] * W[k * N + n];
    if (RELU) acc = fmaxf(acc, 0.0f);
    out[g * N + n] = acc;
}

// ---------------------------------------------------------------------------
// Launch: kernel launches ONLY — no CUDA runtime API calls in this function.
// ---------------------------------------------------------------------------
static inline int cdiv(int a, int b) { return (a + b - 1) / b; }

extern "C" void kernel_launch(void* const* d_in, const int* in_sizes, int n_in,
                              void* d_out, int out_size) {
    const float* nodes = (const float*)d_in[0];
    const int*   eidx  = (const int*)d_in[1];     // int32 (JAX default, x64 off)
    const float* eattr = (const float*)d_in[2];
    const float* u     = (const float*)d_in[3];
    const int*   batch = (const int*)d_in[4];     // int32

    const float* ew0 = (const float*)d_in[5];
    const float* eb0 = (const float*)d_in[6];
    const float* ew1 = (const float*)d_in[7];
    const float* eb1 = (const float*)d_in[8];
    const float* ew2 = (const float*)d_in[9];
    const float* eb2 = (const float*)d_in[10];
    const float* nw0 = (const float*)d_in[11];
    const float* nb0 = (const float*)d_in[12];
    const float* nw1 = (const float*)d_in[13];
    const float* nb1 = (const float*)d_in[14];
    const float* nw2 = (const float*)d_in[15];
    const float* nb2 = (const float*)d_in[16];
    const float* gw0 = (const float*)d_in[17];
    const float* gb0 = (const float*)d_in[18];
    const float* gw1 = (const float*)d_in[19];
    const float* gb1 = (const float*)d_in[20];
    const float* gw2 = (const float*)d_in[21];
    const float* gb2 = (const float*)d_in[22];

    const int* erow = eidx;
    const int* ecol = eidx + N_EDGES;

    float* out_nodes = (float*)d_out;                              // [30000,128]
    float* out_edges = out_nodes + (size_t)N_NODES * DIM;          // [300000,128]
    float* out_glob  = out_edges + (size_t)N_EDGES * DIM;          // [128,128]

    // 1) zero accumulators (fresh each call for determinism across replays)
    zero_all_kernel<<<cdiv(NZ_TOT, 256), 256>>>();

    // 2) edge MLP: 512 -> 256 -> 256 -> 128
    {
        dim3 blk(256);
        dim3 g0(2, cdiv(N_EDGES, 128));
        gemm_kernel<1, true><<<g0, blk>>>(N_EDGES, 512, 256, ew0, eb0,
                                          -1, nullptr, 0, 0, nullptr,
                                          nodes, erow, ecol, eattr, u, batch);
        gemm_kernel<0, true><<<g0, blk>>>(N_EDGES, 256, 256, ew1, eb1,
                                          0, nullptr, 256, 1, nullptr,
                                          nullptr, nullptr, nullptr, nullptr,
                                          nullptr, nullptr);
        dim3 g1(1, cdiv(N_EDGES, 128));
        gemm_kernel<0, false><<<g1, blk>>>(N_EDGES, 256, 128, ew2, eb2,
                                           1, nullptr, 256, -1, out_edges,
                                           nullptr, nullptr, nullptr, nullptr,
                                           nullptr, nullptr);
    }

    // 3) scatter edges -> per-node agg/count + per-graph edge sums/counts
    {
        long long total = (long long)N_EDGES * DIM;
        int blocks = (int)((total + 255) / 256);
        scatter_edges_kernel<<<blocks, 256>>>(out_edges, erow, ecol, batch);
    }

    // 4) node MLP: 384 -> 256 -> 256 -> 128 (agg mean fused into gather)
    {
        dim3 blk(256);
        dim3 g0(2, cdiv(N_NODES, 128));
        gemm_kernel<2, true><<<g0, blk>>>(N_NODES, 384, 256, nw0, nb0,
                                          -1, nullptr, 0, 0, nullptr,
                                          nodes, nullptr, nullptr, nullptr,
                                          u, batch);
        gemm_kernel<0, true><<<g0, blk>>>(N_NODES, 256, 256, nw1, nb1,
                                          0, nullptr, 256, 1, nullptr,
                                          nullptr, nullptr, nullptr, nullptr,
                                          nullptr, nullptr);
        dim3 g1(1, cdiv(N_NODES, 128));
        gemm_kernel<0, false><<<g1, blk>>>(N_NODES, 256, 128, nw2, nb2,
                                           1, nullptr, 256, -1, out_nodes,
                                           nullptr, nullptr, nullptr, nullptr,
                                           nullptr, nullptr);
    }

    // 5) scatter nodes -> per-graph node sums/counts
    {
        long long total = (long long)N_NODES * DIM;
        int blocks = (int)((total + 255) / 256);
        scatter_nodes_kernel<<<blocks, 256>>>(out_nodes, batch);
    }

    // 6) build global input [u | mean(nodes_out) | mean(edges_out)]
    build_gin_kernel<<<cdiv(N_GRAPHS * 384, 256), 256>>>(u);

    // 7) global MLP: 384 -> 256 -> 256 -> 128 (row-parallel, M=128)
    small_mlp_kernel<true><<<N_GRAPHS, 256>>>(2, 384, 256, gw0, gb0, 3, nullptr);
    small_mlp_kernel<true><<<N_GRAPHS, 256>>>(3, 256, 256, gw1, gb1, 4, nullptr);
    small_mlp_kernel<false><<<N_GRAPHS, 128>>>(4, 256, 128, gw2, gb2, -1, out_glob);

    (void)in_sizes; (void)n_in; (void)out_size;
}

// round 8
// speedup vs baseline: 2.3459x; 2.3459x over previous
#include <cuda_runtime.h>
#include <cuda_bf16.h>
#include <cstdint>

#define N_NODES  30000
#define N_EDGES  300000
#define N_GRAPHS 128
#define DIM      128

// ---------------------------------------------------------------------------
// Scratch: __device__ globals, referenced ONLY from device code.
// ---------------------------------------------------------------------------
__device__ float g_bufA[(size_t)N_EDGES * 256];   // hidden ping
__device__ float g_bufB[(size_t)N_EDGES * 256];   // hidden pong
__device__ float g_agg[(size_t)N_NODES * DIM];    // scatter-sum of edges_out by col
__device__ float g_cnt[N_NODES];                  // edge count per node
__device__ float g_gsn[N_GRAPHS * DIM];           // per-graph node sums
__device__ float g_gse[N_GRAPHS * DIM];           // per-graph edge sums
__device__ float g_gcn[N_GRAPHS];                 // per-graph node counts
__device__ float g_gce[N_GRAPHS];                 // per-graph edge counts
__device__ float g_gin[N_GRAPHS * 384];           // global MLP input
__device__ float g_gh0[N_GRAPHS * 256];
__device__ float g_gh1[N_GRAPHS * 256];

__device__ __forceinline__ float* buf_ptr(int sel, float* def) {
    if (sel == 0) return g_bufA;
    if (sel == 1) return g_bufB;
    return def;
}
__device__ __forceinline__ const float* cbuf_ptr(int sel, const float* def) {
    if (sel == 0) return g_bufA;
    if (sel == 1) return g_bufB;
    if (sel == 2) return g_gin;
    if (sel == 3) return g_gh0;
    if (sel == 4) return g_gh1;
    return def;
}

// packed fp32x2 FMA
__device__ __forceinline__ void ffma2(unsigned long long& d,
                                      unsigned long long a,
                                      unsigned long long b) {
    asm("fma.rn.f32x2 %0, %1, %2, %0;" : "+l"(d) : "l"(a), "l"(b));
}

// ---------------------------------------------------------------------------
// Zero accumulators
// ---------------------------------------------------------------------------
#define NZ_AGG (N_NODES * DIM)
#define NZ_1   (NZ_AGG + N_NODES)
#define NZ_2   (NZ_1 + N_GRAPHS * DIM)
#define NZ_3   (NZ_2 + N_GRAPHS * DIM)
#define NZ_4   (NZ_3 + N_GRAPHS)
#define NZ_TOT (NZ_4 + N_GRAPHS)

__global__ void zero_all_kernel() {
    int i = blockIdx.x * blockDim.x + threadIdx.x;
    if (i < NZ_AGG)      g_agg[i] = 0.0f;
    else if (i < NZ_1)   g_cnt[i - NZ_AGG] = 0.0f;
    else if (i < NZ_2)   g_gsn[i - NZ_1] = 0.0f;
    else if (i < NZ_3)   g_gse[i - NZ_2] = 0.0f;
    else if (i < NZ_4)   g_gcn[i - NZ_3] = 0.0f;
    else if (i < NZ_TOT) g_gce[i - NZ_4] = 0.0f;
}

// ---------------------------------------------------------------------------
// Vec4 gathered X loads. Section boundaries are multiples of 128 and k0 is a
// multiple of BK=16, so an entire BK-slab lies in one section -> branch is
// uniform per k0 iteration and each load is a single aligned LDG.128.
// ---------------------------------------------------------------------------
template <int MODE>
__device__ __forceinline__ float4 load_x4(
    int m, int k, const float* __restrict__ X, int ldx,
    const float* __restrict__ nodes,
    const int* __restrict__ erow, const int* __restrict__ ecol,
    const float* __restrict__ eattr,
    const float* __restrict__ u, const int* __restrict__ batch) {
    if (MODE == 0) {
        return *(const float4*)&X[(size_t)m * ldx + k];
    } else if (MODE == 1) {
        if (k < 128) {
            return *(const float4*)&nodes[(size_t)erow[m] * 128 + k];
        } else if (k < 256) {
            return *(const float4*)&nodes[(size_t)ecol[m] * 128 + (k - 128)];
        } else if (k < 384) {
            return *(const float4*)&eattr[(size_t)m * 128 + (k - 256)];
        } else {
            return *(const float4*)&u[batch[erow[m]] * 128 + (k - 384)];
        }
    } else {
        if (k < 128) {
            return *(const float4*)&nodes[(size_t)m * 128 + k];
        } else if (k < 256) {
            float r = __frcp_rn(fmaxf(g_cnt[m], 1.0f));
            float4 a = *(const float4*)&g_agg[(size_t)m * 128 + (k - 128)];
            return make_float4(a.x * r, a.y * r, a.z * r, a.w * r);
        } else {
            return *(const float4*)&u[batch[m] * 128 + (k - 256)];
        }
    }
}

// ---------------------------------------------------------------------------
// Pipelined fused-gather GEMM: out[M,N] = act(X[M,K] @ W[K,N] + b)
// BM=BN=128, BK=16, 256 thr, 8x8 outputs/thread (4 m-pairs x 8 n) in f32x2.
// Thread's n columns: {32q + 2tx + r} -> conflict-free dup'd-W SMEM chunks.
// Double-buffered, register-staged, ONE __syncthreads per k-iteration.
// ---------------------------------------------------------------------------
template <int MODE, bool RELU>
__global__ void __launch_bounds__(256)
gemm_kernel(int M, int K, int N,
            const float* __restrict__ W, const float* __restrict__ bias,
            int xsel, const float* Xdef, int ldx,
            int osel, float* Odef,
            const float* __restrict__ nodes,
            const int* __restrict__ erow, const int* __restrict__ ecol,
            const float* __restrict__ eattr,
            const float* __restrict__ u, const int* __restrict__ batch) {
    constexpr int BM = 128, BN = 128, BK = 16;
    constexpr int XS_LD = 128;   // [k][m] transposed X tile
    constexpr int WS_LD = 256;   // duplicated W row: chunk c (16B) = (w[2c],w[2c],w[2c+1],w[2c+1])

    __shared__ __align__(16) float Xs[2][BK * XS_LD];    // 2 x 8 KB
    __shared__ __align__(16) float Wsb[2][BK * WS_LD];   // 2 x 16 KB  (total 48 KB)

    const float* X = cbuf_ptr(xsel, Xdef);
    float* out = buf_ptr(osel, Odef);

    const int tid = threadIdx.x;
    const int tx = tid & 15;               // n-chunk lane
    const int ty = tid >> 4;               // m-group
    const int m0 = ty * 8;
    const int wid = tid >> 5;              // warp: W rows 2*wid, 2*wid+1
    const int lid = tid & 31;
    const int blockM = blockIdx.y * BM;
    const int blockN = blockIdx.x * BN;

    unsigned long long acc[4][8];
#pragma unroll
    for (int i = 0; i < 4; ++i)
#pragma unroll
        for (int j = 0; j < 8; ++j) acc[i][j] = 0ull;

    const int T = K / BK;
    float4 xv[2];
    float2 wv[4];

    // ---- stage loaders (registers) ----
    auto load_frags = [&](int t) {
        const int k0 = t * BK;
#pragma unroll
        for (int it = 0; it < 2; ++it) {
            int f4 = tid + it * 256;          // 512 float4 = 128 m x 4 kq
            int m = f4 >> 2;
            int kq = f4 & 3;
            int gm = blockM + m;
            if (gm < M)
                xv[it] = load_x4<MODE>(gm, k0 + kq * 4, X, ldx, nodes,
                                       erow, ecol, eattr, u, batch);
            else
                xv[it] = make_float4(0.f, 0.f, 0.f, 0.f);
        }
#pragma unroll
        for (int rr = 0; rr < 2; ++rr) {
            int krow = k0 + 2 * wid + rr;
#pragma unroll
            for (int q = 0; q < 2; ++q) {
                int n = blockN + (q * 32 + lid) * 2;
                wv[rr * 2 + q] = *(const float2*)&W[(size_t)krow * N + n];
            }
        }
    };
    auto store_frags = [&](int b) {
#pragma unroll
        for (int it = 0; it < 2; ++it) {
            int f4 = tid + it * 256;
            int m = f4 >> 2;
            int kq = f4 & 3;
            float* xs = &Xs[b][(kq * 4) * XS_LD + m];
            xs[0 * XS_LD] = xv[it].x;
            xs[1 * XS_LD] = xv[it].y;
            xs[2 * XS_LD] = xv[it].z;
            xs[3 * XS_LD] = xv[it].w;
        }
#pragma unroll
        for (int rr = 0; rr < 2; ++rr) {
            int r = 2 * wid + rr;
#pragma unroll
            for (int q = 0; q < 2; ++q) {
                float2 v = wv[rr * 2 + q];
                // contiguous chunk store: lanes cover 512B, conflict-free
                *(float4*)&Wsb[b][r * WS_LD + (q * 32 + lid) * 4] =
                    make_float4(v.x, v.x, v.y, v.y);
            }
        }
    };

    // ---- prologue ----
    load_frags(0);
    store_frags(0);
    __syncthreads();

    // ---- mainloop: load(t+1) | compute(t) | store(t+1) | sync ----
    for (int t = 0; t < T; ++t) {
        const int cur = t & 1;
        if (t + 1 < T) load_frags(t + 1);

#pragma unroll
        for (int kk = 0; kk < BK; ++kk) {
            const float* xr = &Xs[cur][kk * XS_LD + m0];
            ulonglong2 xa = *(const ulonglong2*)xr;         // m-pairs 0,1
            ulonglong2 xb = *(const ulonglong2*)(xr + 4);   // m-pairs 2,3
            unsigned long long xp[4] = {xa.x, xa.y, xb.x, xb.y};
            unsigned long long wp[8];
#pragma unroll
            for (int i = 0; i < 4; ++i) {
                ulonglong2 wc = *(const ulonglong2*)
                    &Wsb[cur][kk * WS_LD + (i * 16 + tx) * 4];
                wp[2 * i] = wc.x;
                wp[2 * i + 1] = wc.y;
            }
#pragma unroll
            for (int i = 0; i < 4; ++i)
#pragma unroll
                for (int j = 0; j < 8; ++j) ffma2(acc[i][j], xp[i], wp[j]);
        }

        if (t + 1 < T) {
            store_frags(1 - cur);
            __syncthreads();
        }
    }

    // ---- epilogue: bias + act + store (4 x float2 per row) ----
    // thread's n column for pair j: blockN + 32*(j>>1) + 2*tx + (j&1)
    float bv[8];
#pragma unroll
    for (int j = 0; j < 8; ++j)
        bv[j] = bias[blockN + 32 * (j >> 1) + 2 * tx + (j & 1)];

#pragma unroll
    for (int i = 0; i < 4; ++i) {
#pragma unroll
        for (int p = 0; p < 2; ++p) {
            int gm = blockM + m0 + 2 * i + p;
            if (gm >= M) continue;
            float vals[8];
#pragma unroll
            for (int j = 0; j < 8; ++j) {
                unsigned long long v = acc[i][j];
                unsigned int bits = p ? (unsigned int)(v >> 32) : (unsigned int)v;
                float f = __uint_as_float(bits) + bv[j];
                if (RELU) f = fmaxf(f, 0.0f);
                vals[j] = f;
            }
            float* orow = &out[(size_t)gm * N + blockN + 2 * tx];
#pragma unroll
            for (int q = 0; q < 4; ++q)
                *(float2*)&orow[32 * q] = make_float2(vals[2 * q], vals[2 * q + 1]);
        }
    }
}

// ---------------------------------------------------------------------------
// Scatter kernels
// ---------------------------------------------------------------------------
__global__ void scatter_edges_kernel(const float* __restrict__ eo,
                                     const int* __restrict__ erow,
                                     const int* __restrict__ ecol,
                                     const int* __restrict__ batch) {
    long long idx = (long long)blockIdx.x * blockDim.x + threadIdx.x;
    if (idx >= (long long)N_EDGES * DIM) return;
    int e = (int)(idx >> 7);
    int d = (int)(idx & 127);
    float v = eo[idx];
    int c = ecol[e];
    atomicAdd(&g_agg[(size_t)c * 128 + d], v);
    int g = batch[erow[e]];
    atomicAdd(&g_gse[g * 128 + d], v);
    if (d == 0) {
        atomicAdd(&g_cnt[c], 1.0f);
        atomicAdd(&g_gce[g], 1.0f);
    }
}

__global__ void scatter_nodes_kernel(const float* __restrict__ no,
                                     const int* __restrict__ batch) {
    long long idx = (long long)blockIdx.x * blockDim.x + threadIdx.x;
    if (idx >= (long long)N_NODES * DIM) return;
    int n = (int)(idx >> 7);
    int d = (int)(idx & 127);
    float v = no[idx];
    int g = batch[n];
    atomicAdd(&g_gsn[g * 128 + d], v);
    if (d == 0) atomicAdd(&g_gcn[g], 1.0f);
}

__global__ void build_gin_kernel(const float* __restrict__ u) {
    int idx = blockIdx.x * blockDim.x + threadIdx.x;
    if (idx >= N_GRAPHS * 384) return;
    int g = idx / 384;
    int k = idx - g * 384;
    float v;
    if (k < 128) v = u[g * 128 + k];
    else if (k < 256) v = g_gsn[g * 128 + (k - 128)] / fmaxf(g_gcn[g], 1.0f);
    else v = g_gse[g * 128 + (k - 256)] / fmaxf(g_gce[g], 1.0f);
    g_gin[idx] = v;
}

// ---------------------------------------------------------------------------
// Tiny row-parallel global MLP
// ---------------------------------------------------------------------------
template <bool RELU>
__global__ void small_mlp_kernel(int xsel, int K, int N,
                                 const float* __restrict__ W, const float* __restrict__ b,
                                 int osel, float* Odef) {
    __shared__ float xs[384];
    const float* X = cbuf_ptr(xsel, nullptr);
    float* out;
    if (osel == 3) out = g_gh0;
    else if (osel == 4) out = g_gh1;
    else out = Odef;
    int g = blockIdx.x;
    for (int k = threadIdx.x; k < K; k += blockDim.x) xs[k] = X[g * K + k];
    __syncthreads();
    int n = threadIdx.x;
    float acc = b[n];
#pragma unroll 4
    for (int k = 0; k < K; ++k) acc += xs[k] * W[k * N + n];
    if (RELU) acc = fmaxf(acc, 0.0f);
    out[g * N + n] = acc;
}

// ---------------------------------------------------------------------------
// Launch: kernel launches ONLY
// ---------------------------------------------------------------------------
static inline int cdiv(int a, int b) { return (a + b - 1) / b; }

extern "C" void kernel_launch(void* const* d_in, const int* in_sizes, int n_in,
                              void* d_out, int out_size) {
    const float* nodes = (const float*)d_in[0];
    const int*   eidx  = (const int*)d_in[1];
    const float* eattr = (const float*)d_in[2];
    const float* u     = (const float*)d_in[3];
    const int*   batch = (const int*)d_in[4];

    const float* ew0 = (const float*)d_in[5];
    const float* eb0 = (const float*)d_in[6];
    const float* ew1 = (const float*)d_in[7];
    const float* eb1 = (const float*)d_in[8];
    const float* ew2 = (const float*)d_in[9];
    const float* eb2 = (const float*)d_in[10];
    const float* nw0 = (const float*)d_in[11];
    const float* nb0 = (const float*)d_in[12];
    const float* nw1 = (const float*)d_in[13];
    const float* nb1 = (const float*)d_in[14];
    const float* nw2 = (const float*)d_in[15];
    const float* nb2 = (const float*)d_in[16];
    const float* gw0 = (const float*)d_in[17];
    const float* gb0 = (const float*)d_in[18];
    const float* gw1 = (const float*)d_in[19];
    const float* gb1 = (const float*)d_in[20];
    const float* gw2 = (const float*)d_in[21];
    const float* gb2 = (const float*)d_in[22];

    const int* erow = eidx;
    const int* ecol = eidx + N_EDGES;

    float* out_nodes = (float*)d_out;
    float* out_edges = out_nodes + (size_t)N_NODES * DIM;
    float* out_glob  = out_edges + (size_t)N_EDGES * DIM;

    zero_all_kernel<<<cdiv(NZ_TOT, 256), 256>>>();

    // edge MLP: 512 -> 256 -> 256 -> 128
    {
        dim3 blk(256);
        dim3 g0(2, cdiv(N_EDGES, 128));
        gemm_kernel<1, true><<<g0, blk>>>(N_EDGES, 512, 256, ew0, eb0,
                                          -1, nullptr, 0, 0, nullptr,
                                          nodes, erow, ecol, eattr, u, batch);
        gemm_kernel<0, true><<<g0, blk>>>(N_EDGES, 256, 256, ew1, eb1,
                                          0, nullptr, 256, 1, nullptr,
                                          nullptr, nullptr, nullptr, nullptr,
                                          nullptr, nullptr);
        dim3 g1(1, cdiv(N_EDGES, 128));
        gemm_kernel<0, false><<<g1, blk>>>(N_EDGES, 256, 128, ew2, eb2,
                                           1, nullptr, 256, -1, out_edges,
                                           nullptr, nullptr, nullptr, nullptr,
                                           nullptr, nullptr);
    }

    {
        long long total = (long long)N_EDGES * DIM;
        scatter_edges_kernel<<<(int)((total + 255) / 256), 256>>>(out_edges, erow, ecol, batch);
    }

    // node MLP: 384 -> 256 -> 256 -> 128
    {
        dim3 blk(256);
        dim3 g0(2, cdiv(N_NODES, 128));
        gemm_kernel<2, true><<<g0, blk>>>(N_NODES, 384, 256, nw0, nb0,
                                          -1, nullptr, 0, 0, nullptr,
                                          nodes, nullptr, nullptr, nullptr,
                                          u, batch);
        gemm_kernel<0, true><<<g0, blk>>>(N_NODES, 256, 256, nw1, nb1,
                                          0, nullptr, 256, 1, nullptr,
                                          nullptr, nullptr, nullptr, nullptr,
                                          nullptr, nullptr);
        dim3 g1(1, cdiv(N_NODES, 128));
        gemm_kernel<0, false><<<g1, blk>>>(N_NODES, 256, 128, nw2, nb2,
                                           1, nullptr, 256, -1, out_nodes,
                                           nullptr, nullptr, nullptr, nullptr,
                                           nullptr, nullptr);
    }

    {
        long long total = (long long)N_NODES * DIM;
        scatter_nodes_kernel<<<(int)((total + 255) / 256), 256>>>(out_nodes, batch);
    }

    build_gin_kernel<<<cdiv(N_GRAPHS * 384, 256), 256>>>(u);

    small_mlp_kernel<true><<<N_GRAPHS, 256>>>(2, 384, 256, gw0, gb0, 3, nullptr);
    small_mlp_kernel<true><<<N_GRAPHS, 256>>>(3, 256, 256, gw1, gb1, 4, nullptr);
    small_mlp_kernel<false><<<N_GRAPHS, 128>>>(4, 256, 128, gw2, gb2, -1, out_glob);

    (void)in_sizes; (void)n_in; (void)out_size;
}

// round 11
// speedup vs baseline: 2.7076x; 1.1542x over previous
#include <cuda_runtime.h>
#include <cuda_bf16.h>
#include <cstdint>

#define N_NODES  30000
#define N_EDGES  300000
#define N_GRAPHS 128
#define DIM      128

// ---------------------------------------------------------------------------
// Scratch: __device__ globals, referenced ONLY from device code.
// ---------------------------------------------------------------------------
__device__ float g_bufA[(size_t)N_EDGES * 256];   // hidden ping
__device__ float g_bufB[(size_t)N_EDGES * 256];   // hidden pong
__device__ float g_agg[(size_t)N_NODES * DIM];    // scatter-sum of edges_out by col
__device__ float g_cnt[N_NODES];                  // edge count per node
__device__ float g_gsn[N_GRAPHS * DIM];           // per-graph node sums
__device__ float g_gse[N_GRAPHS * DIM];           // per-graph edge sums
__device__ float g_gcn[N_GRAPHS];                 // per-graph node counts
__device__ float g_gce[N_GRAPHS];                 // per-graph edge counts
__device__ float g_gin[N_GRAPHS * 384];           // global MLP input
__device__ float g_gh0[N_GRAPHS * 256];
__device__ float g_gh1[N_GRAPHS * 256];

__device__ __forceinline__ float* buf_ptr(int sel, float* def) {
    if (sel == 0) return g_bufA;
    if (sel == 1) return g_bufB;
    return def;
}
__device__ __forceinline__ const float* cbuf_ptr(int sel, const float* def) {
    if (sel == 0) return g_bufA;
    if (sel == 1) return g_bufB;
    if (sel == 2) return g_gin;
    if (sel == 3) return g_gh0;
    if (sel == 4) return g_gh1;
    return def;
}

// packed fp32x2 FMA
__device__ __forceinline__ void ffma2(unsigned long long& d,
                                      unsigned long long a,
                                      unsigned long long b) {
    asm("fma.rn.f32x2 %0, %1, %2, %0;" : "+l"(d) : "l"(a), "l"(b));
}

// ---------------------------------------------------------------------------
// Zero accumulators
// ---------------------------------------------------------------------------
#define NZ_AGG (N_NODES * DIM)
#define NZ_1   (NZ_AGG + N_NODES)
#define NZ_2   (NZ_1 + N_GRAPHS * DIM)
#define NZ_3   (NZ_2 + N_GRAPHS * DIM)
#define NZ_4   (NZ_3 + N_GRAPHS)
#define NZ_TOT (NZ_4 + N_GRAPHS)

__global__ void zero_all_kernel() {
    int i = blockIdx.x * blockDim.x + threadIdx.x;
    if (i < NZ_AGG)      g_agg[i] = 0.0f;
    else if (i < NZ_1)   g_cnt[i - NZ_AGG] = 0.0f;
    else if (i < NZ_2)   g_gsn[i - NZ_1] = 0.0f;
    else if (i < NZ_3)   g_gse[i - NZ_2] = 0.0f;
    else if (i < NZ_4)   g_gcn[i - NZ_3] = 0.0f;
    else if (i < NZ_TOT) g_gce[i - NZ_4] = 0.0f;
}

// ---------------------------------------------------------------------------
// Vec4 gathered X loads. Section boundaries are multiples of 128 and k0 is a
// multiple of BK=16, so an entire BK-slab lies in one section -> branch is
// uniform per k0 iteration and each load is a single aligned LDG.128.
// ---------------------------------------------------------------------------
template <int MODE>
__device__ __forceinline__ float4 load_x4(
    int m, int k, const float* __restrict__ X, int ldx,
    const float* __restrict__ nodes,
    const int* __restrict__ erow, const int* __restrict__ ecol,
    const float* __restrict__ eattr,
    const float* __restrict__ u, const int* __restrict__ batch) {
    if (MODE == 0) {
        return *(const float4*)&X[(size_t)m * ldx + k];
    } else if (MODE == 1) {
        if (k < 128) {
            return *(const float4*)&nodes[(size_t)erow[m] * 128 + k];
        } else if (k < 256) {
            return *(const float4*)&nodes[(size_t)ecol[m] * 128 + (k - 128)];
        } else if (k < 384) {
            return *(const float4*)&eattr[(size_t)m * 128 + (k - 256)];
        } else {
            return *(const float4*)&u[batch[erow[m]] * 128 + (k - 384)];
        }
    } else {
        if (k < 128) {
            return *(const float4*)&nodes[(size_t)m * 128 + k];
        } else if (k < 256) {
            float r = __frcp_rn(fmaxf(g_cnt[m], 1.0f));
            float4 a = *(const float4*)&g_agg[(size_t)m * 128 + (k - 128)];
            return make_float4(a.x * r, a.y * r, a.z * r, a.w * r);
        } else {
            return *(const float4*)&u[batch[m] * 128 + (k - 256)];
        }
    }
}

// ---------------------------------------------------------------------------
// Pipelined fused-gather GEMM: out[M,N] = act(X[M,K] @ W[K,N] + b)
// BM=BN=128, BK=16, 256 thr, 8x8 outputs/thread (4 m-pairs x 8 n) in f32x2.
// Thread's n columns: {32q + 2tx + r} -> conflict-free dup'd-W SMEM chunks.
// Double-buffered, register-staged, ONE __syncthreads per k-iteration.
// R9: __launch_bounds__(256, 2) -> cap 128 regs, 2 CTAs/SM (16 warps) to
// cover the correlated-stall gaps ncu showed at occ=12.5%/issue=34%.
// ---------------------------------------------------------------------------
template <int MODE, bool RELU>
__global__ void __launch_bounds__(256, 2)
gemm_kernel(int M, int K, int N,
            const float* __restrict__ W, const float* __restrict__ bias,
            int xsel, const float* Xdef, int ldx,
            int osel, float* Odef,
            const float* __restrict__ nodes,
            const int* __restrict__ erow, const int* __restrict__ ecol,
            const float* __restrict__ eattr,
            const float* __restrict__ u, const int* __restrict__ batch) {
    constexpr int BM = 128, BN = 128, BK = 16;
    constexpr int XS_LD = 128;   // [k][m] transposed X tile
    constexpr int WS_LD = 256;   // duplicated W row: chunk c (16B) = (w[2c],w[2c],w[2c+1],w[2c+1])

    __shared__ __align__(16) float Xs[2][BK * XS_LD];    // 2 x 8 KB
    __shared__ __align__(16) float Wsb[2][BK * WS_LD];   // 2 x 16 KB  (total 48 KB)

    const float* X = cbuf_ptr(xsel, Xdef);
    float* out = buf_ptr(osel, Odef);

    const int tid = threadIdx.x;
    const int tx = tid & 15;               // n-chunk lane
    const int ty = tid >> 4;               // m-group
    const int m0 = ty * 8;
    const int wid = tid >> 5;              // warp: W rows 2*wid, 2*wid+1
    const int lid = tid & 31;
    const int blockM = blockIdx.y * BM;
    const int blockN = blockIdx.x * BN;

    unsigned long long acc[4][8];
#pragma unroll
    for (int i = 0; i < 4; ++i)
#pragma unroll
        for (int j = 0; j < 8; ++j) acc[i][j] = 0ull;

    const int T = K / BK;
    float4 xv[2];
    float2 wv[4];

    // ---- stage loaders (registers) ----
    auto load_frags = [&](int t) {
        const int k0 = t * BK;
#pragma unroll
        for (int it = 0; it < 2; ++it) {
            int f4 = tid + it * 256;          // 512 float4 = 128 m x 4 kq
            int m = f4 >> 2;
            int kq = f4 & 3;
            int gm = blockM + m;
            if (gm < M)
                xv[it] = load_x4<MODE>(gm, k0 + kq * 4, X, ldx, nodes,
                                       erow, ecol, eattr, u, batch);
            else
                xv[it] = make_float4(0.f, 0.f, 0.f, 0.f);
        }
#pragma unroll
        for (int rr = 0; rr < 2; ++rr) {
            int krow = k0 + 2 * wid + rr;
#pragma unroll
            for (int q = 0; q < 2; ++q) {
                int n = blockN + (q * 32 + lid) * 2;
                wv[rr * 2 + q] = *(const float2*)&W[(size_t)krow * N + n];
            }
        }
    };
    auto store_frags = [&](int b) {
#pragma unroll
        for (int it = 0; it < 2; ++it) {
            int f4 = tid + it * 256;
            int m = f4 >> 2;
            int kq = f4 & 3;
            float* xs = &Xs[b][(kq * 4) * XS_LD + m];
            xs[0 * XS_LD] = xv[it].x;
            xs[1 * XS_LD] = xv[it].y;
            xs[2 * XS_LD] = xv[it].z;
            xs[3 * XS_LD] = xv[it].w;
        }
#pragma unroll
        for (int rr = 0; rr < 2; ++rr) {
            int r = 2 * wid + rr;
#pragma unroll
            for (int q = 0; q < 2; ++q) {
                float2 v = wv[rr * 2 + q];
                // contiguous chunk store: lanes cover 512B, conflict-free
                *(float4*)&Wsb[b][r * WS_LD + (q * 32 + lid) * 4] =
                    make_float4(v.x, v.x, v.y, v.y);
            }
        }
    };

    // ---- prologue ----
    load_frags(0);
    store_frags(0);
    __syncthreads();

    // ---- mainloop: load(t+1) | compute(t) | store(t+1) | sync ----
    for (int t = 0; t < T; ++t) {
        const int cur = t & 1;
        if (t + 1 < T) load_frags(t + 1);

#pragma unroll
        for (int kk = 0; kk < BK; ++kk) {
            const float* xr = &Xs[cur][kk * XS_LD + m0];
            ulonglong2 xa = *(const ulonglong2*)xr;         // m-pairs 0,1
            ulonglong2 xb = *(const ulonglong2*)(xr + 4);   // m-pairs 2,3
            unsigned long long xp[4] = {xa.x, xa.y, xb.x, xb.y};
            unsigned long long wp[8];
#pragma unroll
            for (int i = 0; i < 4; ++i) {
                ulonglong2 wc = *(const ulonglong2*)
                    &Wsb[cur][kk * WS_LD + (i * 16 + tx) * 4];
                wp[2 * i] = wc.x;
                wp[2 * i + 1] = wc.y;
            }
#pragma unroll
            for (int i = 0; i < 4; ++i)
#pragma unroll
                for (int j = 0; j < 8; ++j) ffma2(acc[i][j], xp[i], wp[j]);
        }

        if (t + 1 < T) {
            store_frags(1 - cur);
            __syncthreads();
        }
    }

    // ---- epilogue: bias + act + store (4 x float2 per row) ----
    // thread's n column for pair j: blockN + 32*(j>>1) + 2*tx + (j&1)
    float bv[8];
#pragma unroll
    for (int j = 0; j < 8; ++j)
        bv[j] = bias[blockN + 32 * (j >> 1) + 2 * tx + (j & 1)];

#pragma unroll
    for (int i = 0; i < 4; ++i) {
#pragma unroll
        for (int p = 0; p < 2; ++p) {
            int gm = blockM + m0 + 2 * i + p;
            if (gm >= M) continue;
            float vals[8];
#pragma unroll
            for (int j = 0; j < 8; ++j) {
                unsigned long long v = acc[i][j];
                unsigned int bits = p ? (unsigned int)(v >> 32) : (unsigned int)v;
                float f = __uint_as_float(bits) + bv[j];
                if (RELU) f = fmaxf(f, 0.0f);
                vals[j] = f;
            }
            float* orow = &out[(size_t)gm * N + blockN + 2 * tx];
#pragma unroll
            for (int q = 0; q < 4; ++q)
                *(float2*)&orow[32 * q] = make_float2(vals[2 * q], vals[2 * q + 1]);
        }
    }
}

// ---------------------------------------------------------------------------
// Scatter kernels
// ---------------------------------------------------------------------------
__global__ void scatter_edges_kernel(const float* __restrict__ eo,
                                     const int* __restrict__ erow,
                                     const int* __restrict__ ecol,
                                     const int* __restrict__ batch) {
    long long idx = (long long)blockIdx.x * blockDim.x + threadIdx.x;
    if (idx >= (long long)N_EDGES * DIM) return;
    int e = (int)(idx >> 7);
    int d = (int)(idx & 127);
    float v = eo[idx];
    int c = ecol[e];
    atomicAdd(&g_agg[(size_t)c * 128 + d], v);
    int g = batch[erow[e]];
    atomicAdd(&g_gse[g * 128 + d], v);
    if (d == 0) {
        atomicAdd(&g_cnt[c], 1.0f);
        atomicAdd(&g_gce[g], 1.0f);
    }
}

__global__ void scatter_nodes_kernel(const float* __restrict__ no,
                                     const int* __restrict__ batch) {
    long long idx = (long long)blockIdx.x * blockDim.x + threadIdx.x;
    if (idx >= (long long)N_NODES * DIM) return;
    int n = (int)(idx >> 7);
    int d = (int)(idx & 127);
    float v = no[idx];
    int g = batch[n];
    atomicAdd(&g_gsn[g * 128 + d], v);
    if (d == 0) atomicAdd(&g_gcn[g], 1.0f);
}

__global__ void build_gin_kernel(const float* __restrict__ u) {
    int idx = blockIdx.x * blockDim.x + threadIdx.x;
    if (idx >= N_GRAPHS * 384) return;
    int g = idx / 384;
    int k = idx - g * 384;
    float v;
    if (k < 128) v = u[g * 128 + k];
    else if (k < 256) v = g_gsn[g * 128 + (k - 128)] / fmaxf(g_gcn[g], 1.0f);
    else v = g_gse[g * 128 + (k - 256)] / fmaxf(g_gce[g], 1.0f);
    g_gin[idx] = v;
}

// ---------------------------------------------------------------------------
// Tiny row-parallel global MLP
// ---------------------------------------------------------------------------
template <bool RELU>
__global__ void small_mlp_kernel(int xsel, int K, int N,
                                 const float* __restrict__ W, const float* __restrict__ b,
                                 int osel, float* Odef) {
    __shared__ float xs[384];
    const float* X = cbuf_ptr(xsel, nullptr);
    float* out;
    if (osel == 3) out = g_gh0;
    else if (osel == 4) out = g_gh1;
    else out = Odef;
    int g = blockIdx.x;
    for (int k = threadIdx.x; k < K; k += blockDim.x) xs[k] = X[g * K + k];
    __syncthreads();
    int n = threadIdx.x;
    float acc = b[n];
#pragma unroll 4
    for (int k = 0; k < K; ++k) acc += xs[k] * W[k * N + n];
    if (RELU) acc = fmaxf(acc, 0.0f);
    out[g * N + n] = acc;
}

// ---------------------------------------------------------------------------
// Launch: kernel launches ONLY
// ---------------------------------------------------------------------------
static inline int cdiv(int a, int b) { return (a + b - 1) / b; }

extern "C" void kernel_launch(void* const* d_in, const int* in_sizes, int n_in,
                              void* d_out, int out_size) {
    const float* nodes = (const float*)d_in[0];
    const int*   eidx  = (const int*)d_in[1];
    const float* eattr = (const float*)d_in[2];
    const float* u     = (const float*)d_in[3];
    const int*   batch = (const int*)d_in[4];

    const float* ew0 = (const float*)d_in[5];
    const float* eb0 = (const float*)d_in[6];
    const float* ew1 = (const float*)d_in[7];
    const float* eb1 = (const float*)d_in[8];
    const float* ew2 = (const float*)d_in[9];
    const float* eb2 = (const float*)d_in[10];
    const float* nw0 = (const float*)d_in[11];
    const float* nb0 = (const float*)d_in[12];
    const float* nw1 = (const float*)d_in[13];
    const float* nb1 = (const float*)d_in[14];
    const float* nw2 = (const float*)d_in[15];
    const float* nb2 = (const float*)d_in[16];
    const float* gw0 = (const float*)d_in[17];
    const float* gb0 = (const float*)d_in[18];
    const float* gw1 = (const float*)d_in[19];
    const float* gb1 = (const float*)d_in[20];
    const float* gw2 = (const float*)d_in[21];
    const float* gb2 = (const float*)d_in[22];

    const int* erow = eidx;
    const int* ecol = eidx + N_EDGES;

    float* out_nodes = (float*)d_out;
    float* out_edges = out_nodes + (size_t)N_NODES * DIM;
    float* out_glob  = out_edges + (size_t)N_EDGES * DIM;

    zero_all_kernel<<<cdiv(NZ_TOT, 256), 256>>>();

    // edge MLP: 512 -> 256 -> 256 -> 128
    {
        dim3 blk(256);
        dim3 g0(2, cdiv(N_EDGES, 128));
        gemm_kernel<1, true><<<g0, blk>>>(N_EDGES, 512, 256, ew0, eb0,
                                          -1, nullptr, 0, 0, nullptr,
                                          nodes, erow, ecol, eattr, u, batch);
        gemm_kernel<0, true><<<g0, blk>>>(N_EDGES, 256, 256, ew1, eb1,
                                          0, nullptr, 256, 1, nullptr,
                                          nullptr, nullptr, nullptr, nullptr,
                                          nullptr, nullptr);
        dim3 g1(1, cdiv(N_EDGES, 128));
        gemm_kernel<0, false><<<g1, blk>>>(N_EDGES, 256, 128, ew2, eb2,
                                           1, nullptr, 256, -1, out_edges,
                                           nullptr, nullptr, nullptr, nullptr,
                                           nullptr, nullptr);
    }

    {
        long long total = (long long)N_EDGES * DIM;
        scatter_edges_kernel<<<(int)((total + 255) / 256), 256>>>(out_edges, erow, ecol, batch);
    }

    // node MLP: 384 -> 256 -> 256 -> 128
    {
        dim3 blk(256);
        dim3 g0(2, cdiv(N_NODES, 128));
        gemm_kernel<2, true><<<g0, blk>>>(N_NODES, 384, 256, nw0, nb0,
                                          -1, nullptr, 0, 0, nullptr,
                                          nodes, nullptr, nullptr, nullptr,
                                          u, batch);
        gemm_kernel<0, true><<<g0, blk>>>(N_NODES, 256, 256, nw1, nb1,
                                          0, nullptr, 256, 1, nullptr,
                                          nullptr, nullptr, nullptr, nullptr,
                                          nullptr, nullptr);
        dim3 g1(1, cdiv(N_NODES, 128));
        gemm_kernel<0, false><<<g1, blk>>>(N_NODES, 256, 128, nw2, nb2,
                                           1, nullptr, 256, -1, out_nodes,
                                           nullptr, nullptr, nullptr, nullptr,
                                           nullptr, nullptr);
    }

    {
        long long total = (long long)N_NODES * DIM;
        scatter_nodes_kernel<<<(int)((total + 255) / 256), 256>>>(out_nodes, batch);
    }

    build_gin_kernel<<<cdiv(N_GRAPHS * 384, 256), 256>>>(u);

    small_mlp_kernel<true><<<N_GRAPHS, 256>>>(2, 384, 256, gw0, gb0, 3, nullptr);
    small_mlp_kernel<true><<<N_GRAPHS, 256>>>(3, 256, 256, gw1, gb1, 4, nullptr);
    small_mlp_kernel<false><<<N_GRAPHS, 128>>>(4, 256, 128, gw2, gb2, -1, out_glob);

    (void)in_sizes; (void)n_in; (void)out_size;
}

// round 12
// speedup vs baseline: 2.7085x; 1.0003x over previous
#include <cuda_runtime.h>
#include <cuda_bf16.h>
#include <cstdint>

#define N_NODES  30000
#define N_EDGES  300000
#define N_GRAPHS 128
#define DIM      128

// ---------------------------------------------------------------------------
// Scratch: __device__ globals, referenced ONLY from device code.
// ---------------------------------------------------------------------------
__device__ float g_bufA[(size_t)N_EDGES * 256];   // hidden ping
__device__ float g_bufB[(size_t)N_EDGES * 256];   // hidden pong
__device__ float g_agg[(size_t)N_NODES * DIM];    // scatter-sum of edges_out by col
__device__ float g_cnt[N_NODES];                  // edge count per node
__device__ float g_gsn[N_GRAPHS * DIM];           // per-graph node sums
__device__ float g_gse[N_GRAPHS * DIM];           // per-graph edge sums
__device__ float g_gcn[N_GRAPHS];                 // per-graph node counts
__device__ float g_gce[N_GRAPHS];                 // per-graph edge counts
__device__ float g_gin[N_GRAPHS * 384];           // global MLP input
__device__ float g_gh0[N_GRAPHS * 256];
__device__ float g_gh1[N_GRAPHS * 256];

__device__ __forceinline__ float* buf_ptr(int sel, float* def) {
    if (sel == 0) return g_bufA;
    if (sel == 1) return g_bufB;
    return def;
}
__device__ __forceinline__ const float* cbuf_ptr(int sel, const float* def) {
    if (sel == 0) return g_bufA;
    if (sel == 1) return g_bufB;
    if (sel == 2) return g_gin;
    if (sel == 3) return g_gh0;
    if (sel == 4) return g_gh1;
    return def;
}

// packed fp32x2 FMA
__device__ __forceinline__ void ffma2(unsigned long long& d,
                                      unsigned long long a,
                                      unsigned long long b) {
    asm("fma.rn.f32x2 %0, %1, %2, %0;" : "+l"(d) : "l"(a), "l"(b));
}

// ---------------------------------------------------------------------------
// Zero accumulators
// ---------------------------------------------------------------------------
#define NZ_AGG (N_NODES * DIM)
#define NZ_1   (NZ_AGG + N_NODES)
#define NZ_2   (NZ_1 + N_GRAPHS * DIM)
#define NZ_3   (NZ_2 + N_GRAPHS * DIM)
#define NZ_4   (NZ_3 + N_GRAPHS)
#define NZ_TOT (NZ_4 + N_GRAPHS)

__global__ void zero_all_kernel() {
    int i = blockIdx.x * blockDim.x + threadIdx.x;
    if (i < NZ_AGG)      g_agg[i] = 0.0f;
    else if (i < NZ_1)   g_cnt[i - NZ_AGG] = 0.0f;
    else if (i < NZ_2)   g_gsn[i - NZ_1] = 0.0f;
    else if (i < NZ_3)   g_gse[i - NZ_2] = 0.0f;
    else if (i < NZ_4)   g_gcn[i - NZ_3] = 0.0f;
    else if (i < NZ_TOT) g_gce[i - NZ_4] = 0.0f;
}

// ---------------------------------------------------------------------------
// Vec4 gathered X loads. Section boundaries are multiples of 128 and k0 is a
// multiple of BK=16, so an entire BK-slab lies in one section -> branch is
// uniform per k0 iteration and each load is a single aligned LDG.128.
// ---------------------------------------------------------------------------
template <int MODE>
__device__ __forceinline__ float4 load_x4(
    int m, int k, const float* __restrict__ X, int ldx,
    const float* __restrict__ nodes,
    const int* __restrict__ erow, const int* __restrict__ ecol,
    const float* __restrict__ eattr,
    const float* __restrict__ u, const int* __restrict__ batch) {
    if (MODE == 0) {
        return *(const float4*)&X[(size_t)m * ldx + k];
    } else if (MODE == 1) {
        if (k < 128) {
            return *(const float4*)&nodes[(size_t)erow[m] * 128 + k];
        } else if (k < 256) {
            return *(const float4*)&nodes[(size_t)ecol[m] * 128 + (k - 128)];
        } else if (k < 384) {
            return *(const float4*)&eattr[(size_t)m * 128 + (k - 256)];
        } else {
            return *(const float4*)&u[batch[erow[m]] * 128 + (k - 384)];
        }
    } else {
        if (k < 128) {
            return *(const float4*)&nodes[(size_t)m * 128 + k];
        } else if (k < 256) {
            float r = __frcp_rn(fmaxf(g_cnt[m], 1.0f));
            float4 a = *(const float4*)&g_agg[(size_t)m * 128 + (k - 128)];
            return make_float4(a.x * r, a.y * r, a.z * r, a.w * r);
        } else {
            return *(const float4*)&u[batch[m] * 128 + (k - 256)];
        }
    }
}

// ---------------------------------------------------------------------------
// Pipelined fused-gather GEMM: out[M,N] = act(X[M,K] @ W[K,N] + b)
// BM=BN=128, BK=16, 256 thr, 8x8 outputs/thread (4 m-pairs x 8 n) in f32x2.
// Thread's n columns: {32q + 2tx + r} -> conflict-free dup'd-W SMEM chunks.
// Double-buffered, register-staged, ONE __syncthreads per k-iteration.
// R9: __launch_bounds__(256, 2) -> cap 128 regs, 2 CTAs/SM (16 warps) to
// cover the correlated-stall gaps ncu showed at occ=12.5%/issue=34%.
// ---------------------------------------------------------------------------
template <int MODE, bool RELU>
__global__ void __launch_bounds__(256, 2)
gemm_kernel(int M, int K, int N,
            const float* __restrict__ W, const float* __restrict__ bias,
            int xsel, const float* Xdef, int ldx,
            int osel, float* Odef,
            const float* __restrict__ nodes,
            const int* __restrict__ erow, const int* __restrict__ ecol,
            const float* __restrict__ eattr,
            const float* __restrict__ u, const int* __restrict__ batch) {
    constexpr int BM = 128, BN = 128, BK = 16;
    constexpr int XS_LD = 128;   // [k][m] transposed X tile
    constexpr int WS_LD = 256;   // duplicated W row: chunk c (16B) = (w[2c],w[2c],w[2c+1],w[2c+1])

    __shared__ __align__(16) float Xs[2][BK * XS_LD];    // 2 x 8 KB
    __shared__ __align__(16) float Wsb[2][BK * WS_LD];   // 2 x 16 KB  (total 48 KB)

    const float* X = cbuf_ptr(xsel, Xdef);
    float* out = buf_ptr(osel, Odef);

    const int tid = threadIdx.x;
    const int tx = tid & 15;               // n-chunk lane
    const int ty = tid >> 4;               // m-group
    const int m0 = ty * 8;
    const int wid = tid >> 5;              // warp: W rows 2*wid, 2*wid+1
    const int lid = tid & 31;
    const int blockM = blockIdx.y * BM;
    const int blockN = blockIdx.x * BN;

    unsigned long long acc[4][8];
#pragma unroll
    for (int i = 0; i < 4; ++i)
#pragma unroll
        for (int j = 0; j < 8; ++j) acc[i][j] = 0ull;

    const int T = K / BK;
    float4 xv[2];
    float2 wv[4];

    // ---- stage loaders (registers) ----
    auto load_frags = [&](int t) {
        const int k0 = t * BK;
#pragma unroll
        for (int it = 0; it < 2; ++it) {
            int f4 = tid + it * 256;          // 512 float4 = 128 m x 4 kq
            int m = f4 >> 2;
            int kq = f4 & 3;
            int gm = blockM + m;
            if (gm < M)
                xv[it] = load_x4<MODE>(gm, k0 + kq * 4, X, ldx, nodes,
                                       erow, ecol, eattr, u, batch);
            else
                xv[it] = make_float4(0.f, 0.f, 0.f, 0.f);
        }
#pragma unroll
        for (int rr = 0; rr < 2; ++rr) {
            int krow = k0 + 2 * wid + rr;
#pragma unroll
            for (int q = 0; q < 2; ++q) {
                int n = blockN + (q * 32 + lid) * 2;
                wv[rr * 2 + q] = *(const float2*)&W[(size_t)krow * N + n];
            }
        }
    };
    auto store_frags = [&](int b) {
#pragma unroll
        for (int it = 0; it < 2; ++it) {
            int f4 = tid + it * 256;
            int m = f4 >> 2;
            int kq = f4 & 3;
            float* xs = &Xs[b][(kq * 4) * XS_LD + m];
            xs[0 * XS_LD] = xv[it].x;
            xs[1 * XS_LD] = xv[it].y;
            xs[2 * XS_LD] = xv[it].z;
            xs[3 * XS_LD] = xv[it].w;
        }
#pragma unroll
        for (int rr = 0; rr < 2; ++rr) {
            int r = 2 * wid + rr;
#pragma unroll
            for (int q = 0; q < 2; ++q) {
                float2 v = wv[rr * 2 + q];
                // contiguous chunk store: lanes cover 512B, conflict-free
                *(float4*)&Wsb[b][r * WS_LD + (q * 32 + lid) * 4] =
                    make_float4(v.x, v.x, v.y, v.y);
            }
        }
    };

    // ---- prologue ----
    load_frags(0);
    store_frags(0);
    __syncthreads();

    // ---- mainloop: load(t+1) | compute(t) | store(t+1) | sync ----
    for (int t = 0; t < T; ++t) {
        const int cur = t & 1;
        if (t + 1 < T) load_frags(t + 1);

#pragma unroll
        for (int kk = 0; kk < BK; ++kk) {
            const float* xr = &Xs[cur][kk * XS_LD + m0];
            ulonglong2 xa = *(const ulonglong2*)xr;         // m-pairs 0,1
            ulonglong2 xb = *(const ulonglong2*)(xr + 4);   // m-pairs 2,3
            unsigned long long xp[4] = {xa.x, xa.y, xb.x, xb.y};
            unsigned long long wp[8];
#pragma unroll
            for (int i = 0; i < 4; ++i) {
                ulonglong2 wc = *(const ulonglong2*)
                    &Wsb[cur][kk * WS_LD + (i * 16 + tx) * 4];
                wp[2 * i] = wc.x;
                wp[2 * i + 1] = wc.y;
            }
#pragma unroll
            for (int i = 0; i < 4; ++i)
#pragma unroll
                for (int j = 0; j < 8; ++j) ffma2(acc[i][j], xp[i], wp[j]);
        }

        if (t + 1 < T) {
            store_frags(1 - cur);
            __syncthreads();
        }
    }

    // ---- epilogue: bias + act + store (4 x float2 per row) ----
    // thread's n column for pair j: blockN + 32*(j>>1) + 2*tx + (j&1)
    float bv[8];
#pragma unroll
    for (int j = 0; j < 8; ++j)
        bv[j] = bias[blockN + 32 * (j >> 1) + 2 * tx + (j & 1)];

#pragma unroll
    for (int i = 0; i < 4; ++i) {
#pragma unroll
        for (int p = 0; p < 2; ++p) {
            int gm = blockM + m0 + 2 * i + p;
            if (gm >= M) continue;
            float vals[8];
#pragma unroll
            for (int j = 0; j < 8; ++j) {
                unsigned long long v = acc[i][j];
                unsigned int bits = p ? (unsigned int)(v >> 32) : (unsigned int)v;
                float f = __uint_as_float(bits) + bv[j];
                if (RELU) f = fmaxf(f, 0.0f);
                vals[j] = f;
            }
            float* orow = &out[(size_t)gm * N + blockN + 2 * tx];
#pragma unroll
            for (int q = 0; q < 4; ++q)
                *(float2*)&orow[32 * q] = make_float2(vals[2 * q], vals[2 * q + 1]);
        }
    }
}

// ---------------------------------------------------------------------------
// Scatter kernels
// ---------------------------------------------------------------------------
__global__ void scatter_edges_kernel(const float* __restrict__ eo,
                                     const int* __restrict__ erow,
                                     const int* __restrict__ ecol,
                                     const int* __restrict__ batch) {
    long long idx = (long long)blockIdx.x * blockDim.x + threadIdx.x;
    if (idx >= (long long)N_EDGES * DIM) return;
    int e = (int)(idx >> 7);
    int d = (int)(idx & 127);
    float v = eo[idx];
    int c = ecol[e];
    atomicAdd(&g_agg[(size_t)c * 128 + d], v);
    int g = batch[erow[e]];
    atomicAdd(&g_gse[g * 128 + d], v);
    if (d == 0) {
        atomicAdd(&g_cnt[c], 1.0f);
        atomicAdd(&g_gce[g], 1.0f);
    }
}

__global__ void scatter_nodes_kernel(const float* __restrict__ no,
                                     const int* __restrict__ batch) {
    long long idx = (long long)blockIdx.x * blockDim.x + threadIdx.x;
    if (idx >= (long long)N_NODES * DIM) return;
    int n = (int)(idx >> 7);
    int d = (int)(idx & 127);
    float v = no[idx];
    int g = batch[n];
    atomicAdd(&g_gsn[g * 128 + d], v);
    if (d == 0) atomicAdd(&g_gcn[g], 1.0f);
}

__global__ void build_gin_kernel(const float* __restrict__ u) {
    int idx = blockIdx.x * blockDim.x + threadIdx.x;
    if (idx >= N_GRAPHS * 384) return;
    int g = idx / 384;
    int k = idx - g * 384;
    float v;
    if (k < 128) v = u[g * 128 + k];
    else if (k < 256) v = g_gsn[g * 128 + (k - 128)] / fmaxf(g_gcn[g], 1.0f);
    else v = g_gse[g * 128 + (k - 256)] / fmaxf(g_gce[g], 1.0f);
    g_gin[idx] = v;
}

// ---------------------------------------------------------------------------
// Tiny row-parallel global MLP
// ---------------------------------------------------------------------------
template <bool RELU>
__global__ void small_mlp_kernel(int xsel, int K, int N,
                                 const float* __restrict__ W, const float* __restrict__ b,
                                 int osel, float* Odef) {
    __shared__ float xs[384];
    const float* X = cbuf_ptr(xsel, nullptr);
    float* out;
    if (osel == 3) out = g_gh0;
    else if (osel == 4) out = g_gh1;
    else out = Odef;
    int g = blockIdx.x;
    for (int k = threadIdx.x; k < K; k += blockDim.x) xs[k] = X[g * K + k];
    __syncthreads();
    int n = threadIdx.x;
    float acc = b[n];
#pragma unroll 4
    for (int k = 0; k < K; ++k) acc += xs[k] * W[k * N + n];
    if (RELU) acc = fmaxf(acc, 0.0f);
    out[g * N + n] = acc;
}

// ---------------------------------------------------------------------------
// Launch: kernel launches ONLY
// ---------------------------------------------------------------------------
static inline int cdiv(int a, int b) { return (a + b - 1) / b; }

extern "C" void kernel_launch(void* const* d_in, const int* in_sizes, int n_in,
                              void* d_out, int out_size) {
    const float* nodes = (const float*)d_in[0];
    const int*   eidx  = (const int*)d_in[1];
    const float* eattr = (const float*)d_in[2];
    const float* u     = (const float*)d_in[3];
    const int*   batch = (const int*)d_in[4];

    const float* ew0 = (const float*)d_in[5];
    const float* eb0 = (const float*)d_in[6];
    const float* ew1 = (const float*)d_in[7];
    const float* eb1 = (const float*)d_in[8];
    const float* ew2 = (const float*)d_in[9];
    const float* eb2 = (const float*)d_in[10];
    const float* nw0 = (const float*)d_in[11];
    const float* nb0 = (const float*)d_in[12];
    const float* nw1 = (const float*)d_in[13];
    const float* nb1 = (const float*)d_in[14];
    const float* nw2 = (const float*)d_in[15];
    const float* nb2 = (const float*)d_in[16];
    const float* gw0 = (const float*)d_in[17];
    const float* gb0 = (const float*)d_in[18];
    const float* gw1 = (const float*)d_in[19];
    const float* gb1 = (const float*)d_in[20];
    const float* gw2 = (const float*)d_in[21];
    const float* gb2 = (const float*)d_in[22];

    const int* erow = eidx;
    const int* ecol = eidx + N_EDGES;

    float* out_nodes = (float*)d_out;
    float* out_edges = out_nodes + (size_t)N_NODES * DIM;
    float* out_glob  = out_edges + (size_t)N_EDGES * DIM;

    zero_all_kernel<<<cdiv(NZ_TOT, 256), 256>>>();

    // edge MLP: 512 -> 256 -> 256 -> 128
    {
        dim3 blk(256);
        dim3 g0(2, cdiv(N_EDGES, 128));
        gemm_kernel<1, true><<<g0, blk>>>(N_EDGES, 512, 256, ew0, eb0,
                                          -1, nullptr, 0, 0, nullptr,
                                          nodes, erow, ecol, eattr, u, batch);
        gemm_kernel<0, true><<<g0, blk>>>(N_EDGES, 256, 256, ew1, eb1,
                                          0, nullptr, 256, 1, nullptr,
                                          nullptr, nullptr, nullptr, nullptr,
                                          nullptr, nullptr);
        dim3 g1(1, cdiv(N_EDGES, 128));
        gemm_kernel<0, false><<<g1, blk>>>(N_EDGES, 256, 128, ew2, eb2,
                                           1, nullptr, 256, -1, out_edges,
                                           nullptr, nullptr, nullptr, nullptr,
                                           nullptr, nullptr);
    }

    {
        long long total = (long long)N_EDGES * DIM;
        scatter_edges_kernel<<<(int)((total + 255) / 256), 256>>>(out_edges, erow, ecol, batch);
    }

    // node MLP: 384 -> 256 -> 256 -> 128
    {
        dim3 blk(256);
        dim3 g0(2, cdiv(N_NODES, 128));
        gemm_kernel<2, true><<<g0, blk>>>(N_NODES, 384, 256, nw0, nb0,
                                          -1, nullptr, 0, 0, nullptr,
                                          nodes, nullptr, nullptr, nullptr,
                                          u, batch);
        gemm_kernel<0, true><<<g0, blk>>>(N_NODES, 256, 256, nw1, nb1,
                                          0, nullptr, 256, 1, nullptr,
                                          nullptr, nullptr, nullptr, nullptr,
                                          nullptr, nullptr);
        dim3 g1(1, cdiv(N_NODES, 128));
        gemm_kernel<0, false><<<g1, blk>>>(N_NODES, 256, 128, nw2, nb2,
                                           1, nullptr, 256, -1, out_nodes,
                                           nullptr, nullptr, nullptr, nullptr,
                                           nullptr, nullptr);
    }

    {
        long long total = (long long)N_NODES * DIM;
        scatter_nodes_kernel<<<(int)((total + 255) / 256), 256>>>(out_nodes, batch);
    }

    build_gin_kernel<<<cdiv(N_GRAPHS * 384, 256), 256>>>(u);

    small_mlp_kernel<true><<<N_GRAPHS, 256>>>(2, 384, 256, gw0, gb0, 3, nullptr);
    small_mlp_kernel<true><<<N_GRAPHS, 256>>>(3, 256, 256, gw1, gb1, 4, nullptr);
    small_mlp_kernel<false><<<N_GRAPHS, 128>>>(4, 256, 128, gw2, gb2, -1, out_glob);

    (void)in_sizes; (void)n_in; (void)out_size;
}